// round 10
// baseline (speedup 1.0000x reference)
#include <cuda_runtime.h>

// LookupFreeQuantizer — sm_103a, round 8: round 7 + fixed index-store alignment
// (OUT_IDX=655365 is odd -> float2 store was misaligned; use 2 scalar stores).
// Factorized softmax: p(bit_c=+1) = sigmoid(400 z_c),  e_c = exp(-400|z_c|)
//   P0 = prod_c 1/(1+e_c);  per_sample_entropy H_s = -log(P0) + sum_c a_c e_c/(1+e_c)
//   probs[n] = P0 * prod_{c in flipset} e_c  (sparse: only e_c > 1e-7 flips matter;
//   neglected mass <= 1e-6/sample -> avg_entropy abs err ~1e-5, << 1e-3 gate).
// Output (fp32): [ z_q 655360 | loss, commit, ent_loss, pse, avg_ent | indices 65536 ]

#define CH      10
#define HW      1024
#define OUT_SCALARS 655360
#define OUT_IDX     655365
#define THRESH  1e-7f
#define NBLK    256
#define NTHR    128

// Zero-initialized at load; last block re-zeroes after use -> graph-replay safe.
__device__ float        g_avg[1024];
__device__ float        g_ent;
__device__ float        g_commit;
__device__ unsigned int g_count;

__global__ void __launch_bounds__(NTHR)
fused_kernel(const float* __restrict__ z, float* __restrict__ out) {
    __shared__ float we[4], wc[4];
    __shared__ bool  isLast;

    const int tid  = threadIdx.x;
    const int lane = tid & 31;
    const int wrp  = tid >> 5;
    const int s    = (blockIdx.x * NTHR + tid) * 2;    // 2 consecutive samples

    // ---- vectorized load: 2 samples x 10 channels ----
    const int base = (s >> 10) * (CH * HW) + (s & (HW - 1));   // 2-aligned
    const float2* zp = (const float2*)(z + base);
    float2* op = (float2*)(out + base);

    float2 v2[CH];
    #pragma unroll
    for (int c = 0; c < CH; c++) v2[c] = zp[c * (HW / 2)];

    // ---- z_q (sign) store + commitment ----
    float comAcc = 0.f;
    #pragma unroll
    for (int c = 0; c < CH; c++) {
        float2 v = v2[c], sg;
        sg.x = v.x > 0.f ? 1.f : -1.f;
        sg.y = v.y > 0.f ? 1.f : -1.f;
        op[c * (HW / 2)] = sg;
        float dx = sg.x - v.x, dy = sg.y - v.y;
        comAcc = fmaf(dx, dx, comAcc);
        comAcc = fmaf(dy, dy, comAcc);
    }

    // ---- per-sample entropy + index + sparse prob scatter ----
    float entAcc = 0.f;
    #pragma unroll
    for (int j = 0; j < 2; j++) {
        float el[CH];                       // fully unrolled -> registers
        float P0 = 1.f, tailH = 0.f;
        int idx = 0;
        unsigned m = 0;
        #pragma unroll
        for (int c = 0; c < CH; c++) {
            float v  = (j == 0) ? v2[c].x : v2[c].y;
            float a  = 400.f * fabsf(v);
            float ec = __expf(-a);                       // MUFU.EX2
            el[c] = ec;
            float pmaj = __fdividef(1.f, 1.f + ec);      // MUFU.RCP
            tailH = fmaf(a * ec, pmaj, tailH);
            P0 *= pmaj;
            if (ec > THRESH) m |= (1u << c);
            if (v > 0.f)     idx |= (1 << c);
        }
        entAcc += tailH - __logf(P0);       // sum_c log(1+e_c) == -log(P0): 1 LG2/sample
        out[OUT_IDX + s + j] = (float)idx;  // scalar STG.32 (odd base -> no vector store)

        atomicAdd(&g_avg[idx], P0);         // RED.F32, fire-and-forget
        unsigned sub = m;
        while (sub) {                       // rare nonzero flip submasks (~0.3/sample)
            float w = P0;
            #pragma unroll
            for (int c = 0; c < CH; c++)
                if (sub & (1u << c)) w *= el[c];   // predicated FMUL, const index
            atomicAdd(&g_avg[idx ^ (int)sub], w);
            sub = (sub - 1) & m;
        }
    }

    // ---- block reduce entropy + commitment -> 2 REDs ----
    #pragma unroll
    for (int o = 16; o; o >>= 1) {
        entAcc += __shfl_down_sync(0xffffffffu, entAcc, o);
        comAcc += __shfl_down_sync(0xffffffffu, comAcc, o);
    }
    if (lane == 0) { we[wrp] = entAcc; wc[wrp] = comAcc; }
    __syncthreads();
    if (tid == 0) {
        atomicAdd(&g_ent,    we[0] + we[1] + we[2] + we[3]);
        atomicAdd(&g_commit, wc[0] + wc[1] + wc[2] + wc[3]);
    }

    // ---- arrival: bar.sync (CTA order) + one gpu fence by tid0 ----
    __syncthreads();
    if (tid == 0) {
        asm volatile("fence.acq_rel.gpu;" ::: "memory");  // release this block's REDs
        isLast = (atomicAdd(&g_count, 1u) == (unsigned)(gridDim.x - 1));
    }
    __syncthreads();
    if (!isLast) return;
    if (tid == 0)
        asm volatile("fence.acq_rel.gpu;" ::: "memory");  // acquire others' REDs
    __syncthreads();

    // ---- last-block finalize (128 threads, 8 bins each) ----
    float term = 0.f;
    #pragma unroll
    for (int k = 0; k < 8; k++) {
        float p = __ldcg(&g_avg[tid + k * 128]) * (1.f / 65536.f);
        term = fmaf(p, __logf(p + 1e-5f), term);
    }
    #pragma unroll
    for (int o = 16; o; o >>= 1) term += __shfl_down_sync(0xffffffffu, term, o);
    if (lane == 0) we[wrp] = term;
    __syncthreads();
    if (tid == 0) {
        float v = we[0] + we[1] + we[2] + we[3];
        float pse          = __ldcg(&g_ent) * (1.f / 65536.f);
        float avg_entropy  = -v;                        // ENT_GAMMA = 1.0
        float entropy_loss = 0.1f * (pse - avg_entropy);
        float commitment   = 0.25f * (__ldcg(&g_commit) * (1.f / 655360.f));
        out[OUT_SCALARS + 0] = commitment + entropy_loss;  // loss
        out[OUT_SCALARS + 1] = commitment;
        out[OUT_SCALARS + 2] = entropy_loss;
        out[OUT_SCALARS + 3] = pse;
        out[OUT_SCALARS + 4] = avg_entropy;
        g_ent = 0.f;
        g_commit = 0.f;
        g_count = 0u;
    }
    // reset g_avg for the next (graph-replayed) launch
    __syncthreads();
    #pragma unroll
    for (int k = 0; k < 8; k++) g_avg[tid + k * 128] = 0.f;
}

extern "C" void kernel_launch(void* const* d_in, const int* in_sizes, int n_in,
                              void* d_out, int out_size) {
    const float* z = (const float*)d_in[0];
    float* out = (float*)d_out;
    fused_kernel<<<NBLK, NTHR>>>(z, out);
}

// round 11
// speedup vs baseline: 1.9314x; 1.9314x over previous
#include <cuda_runtime.h>

// LookupFreeQuantizer — sm_103a, round 10: round-6 structure (shared histogram,
// 8-warp blocks) + round-7 math (1 LG2/sample entropy), 128 blocks x 256 thr.
// Factorized softmax: p(bit_c=+1) = sigmoid(400 z_c),  e_c = exp(-400|z_c|)
//   P0 = prod_c 1/(1+e_c);  per_sample_entropy H_s = -log(P0) + sum_c a_c e_c/(1+e_c)
//   probs[n] = P0 * prod_{c in flipset} e_c  (sparse: only e_c > 1e-7 flips matter;
//   neglected mass <= 1e-6/sample -> avg_entropy abs err ~1e-5, << 1e-3 gate).
// Output (fp32): [ z_q 655360 | loss, commit, ent_loss, pse, avg_ent | indices 65536 ]

#define CH      10
#define HW      1024
#define OUT_SCALARS 655360
#define OUT_IDX     655365
#define THRESH  1e-7f
#define NBLK    128
#define NTHR    256

// Zero-initialized at load; last block re-zeroes after use -> graph-replay safe.
__device__ float        g_avg[1024];
__device__ float        g_ent;
__device__ float        g_commit;
__device__ unsigned int g_count;

__global__ void __launch_bounds__(NTHR)
fused_kernel(const float* __restrict__ z, float* __restrict__ out) {
    __shared__ float bins[1024];
    __shared__ float we[8], wc[8];
    __shared__ bool  isLast;

    const int tid  = threadIdx.x;
    const int lane = tid & 31;
    const int wrp  = tid >> 5;
    const int s    = (blockIdx.x * NTHR + tid) * 2;    // 2 consecutive samples

    #pragma unroll
    for (int k = 0; k < 4; k++) bins[tid + k * 256] = 0.f;
    __syncthreads();

    // ---- vectorized load: 2 samples x 10 channels ----
    const int base = (s >> 10) * (CH * HW) + (s & (HW - 1));   // 2-aligned
    const float2* zp = (const float2*)(z + base);
    float2* op = (float2*)(out + base);

    float2 v2[CH];
    #pragma unroll
    for (int c = 0; c < CH; c++) v2[c] = zp[c * (HW / 2)];

    // ---- z_q (sign) store + commitment ----
    float comAcc = 0.f;
    #pragma unroll
    for (int c = 0; c < CH; c++) {
        float2 v = v2[c], sg;
        sg.x = v.x > 0.f ? 1.f : -1.f;
        sg.y = v.y > 0.f ? 1.f : -1.f;
        op[c * (HW / 2)] = sg;
        float dx = sg.x - v.x, dy = sg.y - v.y;
        comAcc = fmaf(dx, dx, comAcc);
        comAcc = fmaf(dy, dy, comAcc);
    }

    // ---- per-sample entropy + index + sparse prob scatter (shared histogram) ----
    float entAcc = 0.f;
    #pragma unroll
    for (int j = 0; j < 2; j++) {
        float el[CH];                       // fully unrolled -> registers
        float P0 = 1.f, tailH = 0.f;
        int idx = 0;
        unsigned m = 0;
        #pragma unroll
        for (int c = 0; c < CH; c++) {
            float v  = (j == 0) ? v2[c].x : v2[c].y;
            float a  = 400.f * fabsf(v);
            float ec = __expf(-a);                       // MUFU.EX2
            el[c] = ec;
            float pmaj = __fdividef(1.f, 1.f + ec);      // MUFU.RCP
            tailH = fmaf(a * ec, pmaj, tailH);
            P0 *= pmaj;
            if (ec > THRESH) m |= (1u << c);
            if (v > 0.f)     idx |= (1 << c);
        }
        entAcc += tailH - __logf(P0);       // sum_c log(1+e_c) == -log(P0): 1 LG2/sample
        out[OUT_IDX + s + j] = (float)idx;  // scalar STG.32 (odd base; coalesced)

        atomicAdd(&bins[idx], P0);          // ATOMS, pre-aggregation in smem
        unsigned sub = m;
        while (sub) {                       // rare nonzero flip submasks (~0.3/sample)
            float w = P0;
            #pragma unroll
            for (int c = 0; c < CH; c++)
                if (sub & (1u << c)) w *= el[c];   // predicated FMUL, const index
            atomicAdd(&bins[idx ^ (int)sub], w);
            sub = (sub - 1) & m;
        }
    }

    // ---- block reduce entropy + commitment -> 2 REDs ----
    #pragma unroll
    for (int o = 16; o; o >>= 1) {
        entAcc += __shfl_down_sync(0xffffffffu, entAcc, o);
        comAcc += __shfl_down_sync(0xffffffffu, comAcc, o);
    }
    if (lane == 0) { we[wrp] = entAcc; wc[wrp] = comAcc; }
    __syncthreads();
    if (wrp == 0) {
        float e2 = (lane < 8) ? we[lane] : 0.f;
        float c2 = (lane < 8) ? wc[lane] : 0.f;
        #pragma unroll
        for (int o = 4; o; o >>= 1) {
            e2 += __shfl_down_sync(0xffffffffu, e2, o);
            c2 += __shfl_down_sync(0xffffffffu, c2, o);
        }
        if (lane == 0) {
            atomicAdd(&g_ent, e2);
            atomicAdd(&g_commit, c2);
        }
    }

    // ---- drain nonzero bins to global (coalesced per-lane-distinct RED.F32) ----
    #pragma unroll
    for (int k = 0; k < 4; k++) {
        float v = bins[tid + k * 256];
        if (v != 0.f) atomicAdd(&g_avg[tid + k * 256], v);
    }

    // ---- arrival: bar.sync (CTA order) + one gpu fence by tid0 ----
    __syncthreads();
    if (tid == 0) {
        asm volatile("fence.acq_rel.gpu;" ::: "memory");  // release this block's REDs
        isLast = (atomicAdd(&g_count, 1u) == (unsigned)(gridDim.x - 1));
    }
    __syncthreads();
    if (!isLast) return;
    if (tid == 0)
        asm volatile("fence.acq_rel.gpu;" ::: "memory");  // acquire others' REDs
    __syncthreads();

    // ---- last-block finalize (256 threads, 4 bins each) ----
    float term = 0.f;
    #pragma unroll
    for (int k = 0; k < 4; k++) {
        float p = __ldcg(&g_avg[tid + k * 256]) * (1.f / 65536.f);
        term = fmaf(p, __logf(p + 1e-5f), term);
    }
    #pragma unroll
    for (int o = 16; o; o >>= 1) term += __shfl_down_sync(0xffffffffu, term, o);
    if (lane == 0) we[wrp] = term;
    __syncthreads();
    if (tid == 0) {
        float v = we[0] + we[1] + we[2] + we[3] + we[4] + we[5] + we[6] + we[7];
        float pse          = __ldcg(&g_ent) * (1.f / 65536.f);
        float avg_entropy  = -v;                        // ENT_GAMMA = 1.0
        float entropy_loss = 0.1f * (pse - avg_entropy);
        float commitment   = 0.25f * (__ldcg(&g_commit) * (1.f / 655360.f));
        out[OUT_SCALARS + 0] = commitment + entropy_loss;  // loss
        out[OUT_SCALARS + 1] = commitment;
        out[OUT_SCALARS + 2] = entropy_loss;
        out[OUT_SCALARS + 3] = pse;
        out[OUT_SCALARS + 4] = avg_entropy;
        g_ent = 0.f;
        g_commit = 0.f;
        g_count = 0u;
    }
    // reset g_avg for the next (graph-replayed) launch
    __syncthreads();
    #pragma unroll
    for (int k = 0; k < 4; k++) g_avg[tid + k * 256] = 0.f;
}

extern "C" void kernel_launch(void* const* d_in, const int* in_sizes, int n_in,
                              void* d_out, int out_size) {
    const float* z = (const float*)d_in[0];
    float* out = (float*)d_out;
    fused_kernel<<<NBLK, NTHR>>>(z, out);
}